// round 7
// baseline (speedup 1.0000x reference)
#include <cuda_runtime.h>
#include <cuda_bf16.h>
#include <math.h>
#include <stdint.h>

// Problem constants
#define SEQ    128
#define BATCH  32
#define NTOKEN 32000
#define NINP   1024
#define NHID   1024
#define MROWS  (SEQ * BATCH)          // 4096

// ---------------- scratch (no runtime allocation allowed) ----------------
__device__ float g_xin[MROWS * NHID];        // 16 MB
__device__ float g_hs [MROWS * NHID];        // 16 MB (fp32, scan-internal)
__device__ float g_t32buf[MROWS * NHID];     // 16 MB (tf32 bits: emb32 then hs32)
__device__ float g_decW_t32[NTOKEN * NHID];  // 131 MB (tf32 bits)
__device__ float g_wih_t32[NHID * NINP];     // 4 MB (tf32 bits)
__device__ unsigned g_arrive;
__device__ unsigned g_release;

// ---------------- helpers ----------------
__device__ __forceinline__ uint32_t smem_u32(const void* p) {
    return (uint32_t)__cvta_generic_to_shared(p);
}
__device__ __forceinline__ uint32_t f2tf32(float x) {
    uint32_t r;
    asm("cvt.rna.tf32.f32 %0, %1;" : "=r"(r) : "f"(x));
    return r;
}

#define LDSM_X4(r0, r1, r2, r3, addr) \
    asm volatile("ldmatrix.sync.aligned.m8n8.x4.shared.b16 {%0,%1,%2,%3}, [%4];" \
        : "=r"(r0), "=r"(r1), "=r"(r2), "=r"(r3) : "r"(addr))

// =============== prep: all conversions + gather + barrier reset =============
#define PREP_BLOCKS 2240

__global__ __launch_bounds__(256)
void prep_kernel(const float* __restrict__ dec_W,
                 const float* __restrict__ W_ih,
                 const float* __restrict__ emb_W,
                 const int*   __restrict__ input)
{
    const int bid = blockIdx.x;
    const int t   = threadIdx.x;
    if (bid == 0 && t == 0) { g_arrive = 0u; g_release = 0u; }

    if (bid < 2048) {
        const long n4 = (long)NTOKEN * NHID / 4;
        long i = (long)bid * 256 + t;
        const long stride = 2048L * 256;
        for (; i < n4; i += stride) {
            float4 v = ((const float4*)dec_W)[i];
            uint4 o = { f2tf32(v.x), f2tf32(v.y), f2tf32(v.z), f2tf32(v.w) };
            ((uint4*)g_decW_t32)[i] = o;
        }
    } else if (bid < 2112) {
        const long n4 = (long)NHID * NINP / 4;
        long i = (long)(bid - 2048) * 256 + t;
        const long stride = 64L * 256;
        for (; i < n4; i += stride) {
            float4 v = ((const float4*)W_ih)[i];
            uint4 o = { f2tf32(v.x), f2tf32(v.y), f2tf32(v.z), f2tf32(v.w) };
            ((uint4*)g_wih_t32)[i] = o;
        }
    } else {
        const long n4 = (long)MROWS * NINP / 4;
        long i = (long)(bid - 2112) * 256 + t;
        const long stride = 128L * 256;
        for (; i < n4; i += stride) {
            int row = (int)(i >> 8);          // NINP/4 = 256 float4 per row
            int c4  = (int)(i & 255);
            int tok = input[row];
            float4 v = *(const float4*)(emb_W + (long)tok * NINP + c4 * 4);
            uint4 o = { f2tf32(v.x), f2tf32(v.y), f2tf32(v.z), f2tf32(v.w) };
            *(uint4*)(g_t32buf + (long)row * NINP + c4 * 4) = o;
        }
    }
}

// ============ tf32 mma.sync GEMM with ldmatrix fragments ============
// C[M,N] = A[M,K]*B[N,K]^T + bias.  CTA tile 128x256x32, 8 warps (64x64 each).
// Smem: swizzled 128B rows, chunk' = kc ^ (row&7). 3 buffers, 2 groups in
// flight, ONE __syncthreads per chunk.
#define DBM 128
#define DBN 256
#define DBK 32
#define NSTG 3
#define A_ST (DBM * DBK * 4)   // 16 KB
#define B_ST (DBN * DBK * 4)   // 32 KB
#define DEC_SMEM (NSTG * (A_ST + B_ST))   // 144 KB

__global__ __launch_bounds__(256, 1)
void gemm_tf32_ldsm(const float* __restrict__ A,
                    const float* __restrict__ B,
                    const float* __restrict__ bias,
                    float*       __restrict__ C,
                    int M, int N, int K)
{
    extern __shared__ __align__(1024) char smem[];
    const uint32_t sA = smem_u32(smem);
    const uint32_t sB = sA + NSTG * A_ST;

    const int t    = threadIdx.x;
    const int warp = t >> 5;
    const int lane = t & 31;
    const int m0   = blockIdx.x * DBM;
    const int n0   = blockIdx.y * DBN;
    const int wm   = warp & 1;      // 2 m-subtiles of 64
    const int wn   = warp >> 1;     // 4 n-subtiles of 64
    const int g    = lane >> 2;
    const int tg   = lane & 3;

    // ldmatrix lane geometry
    const int mat = lane >> 3;      // 0..3
    const int sub = lane & 7;       // 0..7

    uint32_t aRowOff[4], aSw[4];
#pragma unroll
    for (int mi = 0; mi < 4; ++mi) {
        int r = wm * 64 + mi * 16 + (mat & 1) * 8 + sub;
        aRowOff[mi] = (uint32_t)(r * 128);
        aSw[mi]     = (uint32_t)(r & 7);
    }
    const uint32_t aMatK = (uint32_t)(mat >> 1);

    // B: 4 LDSM_X4, each covering two 8-row n-groups (2p, 2p+1), k split by mat&1
    uint32_t bRowOff[4], bSw[4];
#pragma unroll
    for (int p = 0; p < 4; ++p) {
        int r = wn * 64 + (p * 2 + (mat >> 1)) * 8 + sub;
        bRowOff[p] = (uint32_t)(r * 128);
        bSw[p]     = (uint32_t)(r & 7);
    }
    const uint32_t bMatK = (uint32_t)(mat & 1);

    float acc[4][8][4];
#pragma unroll
    for (int mi = 0; mi < 4; ++mi)
#pragma unroll
        for (int ni = 0; ni < 8; ++ni)
#pragma unroll
            for (int r = 0; r < 4; ++r) acc[mi][ni][r] = 0.0f;

    auto load_chunk = [&](int c) {
        const int s  = c % NSTG;
        const int k0 = c * DBK;
        // A tile: 128 rows x 8 chunks = 1024
#pragma unroll
        for (int i = 0; i < 4; ++i) {
            int id  = t + i * 256;
            int row = id >> 3;
            int kc  = id & 7;
            uint32_t sw = (uint32_t)(row * 128 + ((kc ^ (row & 7)) << 4));
            uint32_t dst = sA + s * A_ST + sw;
            const float* ga = A + (long)(m0 + row) * K + k0 + kc * 4;
            asm volatile("cp.async.cg.shared.global [%0], [%1], 16;" :: "r"(dst), "l"(ga));
        }
        // B tile: 256 rows x 8 chunks = 2048
#pragma unroll
        for (int i = 0; i < 8; ++i) {
            int id  = t + i * 256;
            int row = id >> 3;
            int kc  = id & 7;
            uint32_t sw = (uint32_t)(row * 128 + ((kc ^ (row & 7)) << 4));
            uint32_t dst = sB + s * B_ST + sw;
            const float* gb = B + (long)(n0 + row) * K + k0 + kc * 4;
            asm volatile("cp.async.cg.shared.global [%0], [%1], 16;" :: "r"(dst), "l"(gb));
        }
        asm volatile("cp.async.commit_group;");
    };

    const int NCHUNK = K / DBK;   // 32
    load_chunk(0);
    load_chunk(1);

    for (int c = 0; c < NCHUNK; ++c) {
        const int buf = c % NSTG;
        asm volatile("cp.async.wait_group 1;");   // chunk c resident
        __syncthreads();                          // the ONLY sync per chunk

        // prefetch chunk c+2 into buf (c-1)%3 (finished by all warps)
        if (c + 2 < NCHUNK) {
            load_chunk(c + 2);
        } else {
            asm volatile("cp.async.commit_group;");   // uniform accounting
        }

        const uint32_t Ab = sA + buf * A_ST;
        const uint32_t Bb = sB + buf * B_ST;

#pragma unroll
        for (int kk = 0; kk < 4; ++kk) {
            uint32_t a[4][4];
            uint32_t b[8][2];
            const uint32_t cA = (uint32_t)(kk * 2) + aMatK;
            const uint32_t cB = (uint32_t)(kk * 2) + bMatK;
#pragma unroll
            for (int mi = 0; mi < 4; ++mi) {
                uint32_t addr = Ab + aRowOff[mi] + (((cA ^ aSw[mi])) << 4);
                LDSM_X4(a[mi][0], a[mi][1], a[mi][2], a[mi][3], addr);
            }
#pragma unroll
            for (int p = 0; p < 4; ++p) {
                uint32_t addr = Bb + bRowOff[p] + (((cB ^ bSw[p])) << 4);
                uint32_t r0, r1, r2, r3;
                LDSM_X4(r0, r1, r2, r3, addr);
                b[2 * p][0] = r0;     b[2 * p][1] = r1;
                b[2 * p + 1][0] = r2; b[2 * p + 1][1] = r3;
            }
#pragma unroll
            for (int mi = 0; mi < 4; ++mi)
#pragma unroll
                for (int ni = 0; ni < 8; ++ni) {
                    asm volatile(
                        "mma.sync.aligned.m16n8k8.row.col.f32.tf32.tf32.f32 "
                        "{%0,%1,%2,%3}, {%4,%5,%6,%7}, {%8,%9}, {%0,%1,%2,%3};\n"
                        : "+f"(acc[mi][ni][0]), "+f"(acc[mi][ni][1]),
                          "+f"(acc[mi][ni][2]), "+f"(acc[mi][ni][3])
                        : "r"(a[mi][0]), "r"(a[mi][1]), "r"(a[mi][2]), "r"(a[mi][3]),
                          "r"(b[ni][0]), "r"(b[ni][1]));
                }
        }
        // no trailing sync: next iteration's wait+sync provides the ordering
    }

    // ---- epilogue: add bias, store ----
#pragma unroll
    for (int mi = 0; mi < 4; ++mi) {
        int rbase = m0 + wm * 64 + mi * 16 + g;
#pragma unroll
        for (int ni = 0; ni < 8; ++ni) {
            int cc = n0 + wn * 64 + ni * 8 + 2 * tg;
            float b0 = bias[cc], b1 = bias[cc + 1];
            float2 v0 = make_float2(acc[mi][ni][0] + b0, acc[mi][ni][1] + b1);
            float2 v1 = make_float2(acc[mi][ni][2] + b0, acc[mi][ni][3] + b1);
            *(float2*)(C + (long)rbase * N + cc)       = v0;
            *(float2*)(C + (long)(rbase + 8) * N + cc) = v1;
        }
    }
}

// ---------------- persistent RNN scan ----------------
__device__ __forceinline__ void grid_barrier(unsigned gen) {
    __syncthreads();
    if (threadIdx.x == 0) {
        __threadfence();
        if (atomicAdd(&g_arrive, 1u) == gridDim.x - 1) {
            g_arrive = 0u;
            __threadfence();
            atomicExch(&g_release, gen);
        } else {
            while (*(volatile unsigned*)&g_release < gen) { }
        }
        __threadfence();
    }
    __syncthreads();
}

// Writes: hs (fp32), hs32 (tf32 bits), hidden_f at s == SEQ-1.
__global__ __launch_bounds__(256)
void scan_kernel(const float* __restrict__ xin,
                 const float* __restrict__ h0,
                 const float* __restrict__ W_hh,
                 const float* __restrict__ b_hh,
                 const float* __restrict__ alpha,
                 float*       __restrict__ hs,
                 float*       __restrict__ hs32,
                 float*       __restrict__ hidden_f)
{
    extern __shared__ float sm[];
    float* Wsh = sm;                  // 8 * 1024
    float* red = sm + 8 * 1024;       // 8 * 32 * 8

    const int t  = threadIdx.x;
    const int jb = blockIdx.x;
    const int j0 = jb * 8;

    {
        const float4* src = (const float4*)(W_hh + (long)j0 * NHID);
        float4* dst = (float4*)Wsh;
        for (int i = t; i < 8 * NHID / 4; i += 256) dst[i] = src[i];
    }
    __syncthreads();

    const int kg = t >> 5;
    const int b  = t & 31;
    const int b2  = t >> 3;
    const int jj2 = t & 7;
    const float bh = b_hh[j0 + jj2];

    for (int s = 0; s < SEQ; ++s) {
        const float* hprev = (s == 0) ? h0 : (hs + (long)(s - 1) * BATCH * NHID);

        float acc[8];
#pragma unroll
        for (int jj = 0; jj < 8; ++jj) acc[jj] = 0.0f;

        const float* hrow  = hprev + (long)b * NHID + kg * 128;
        const float* wbase = &Wsh[kg * 128];
#pragma unroll 8
        for (int k = 0; k < 128; k += 4) {
            float4 hv = *(const float4*)&hrow[k];
#pragma unroll
            for (int jj = 0; jj < 8; ++jj) {
                float4 wv = *(const float4*)&wbase[jj * NHID + k];
                acc[jj] += hv.x * wv.x + hv.y * wv.y + hv.z * wv.z + hv.w * wv.w;
            }
        }

#pragma unroll
        for (int jj = 0; jj < 8; ++jj) red[(kg * 32 + b) * 8 + jj] = acc[jj];
        __syncthreads();

        {
            float sum = 0.0f;
#pragma unroll
            for (int kk = 0; kk < 8; ++kk) sum += red[(kk * 32 + b2) * 8 + jj2];
            long idx = (long)(s * BATCH + b2) * NHID + j0 + jj2;
            float val = xin[idx] + sum + bh;
            float hnew = alpha[s] * tanhf(val);
            hs[idx] = hnew;
            ((uint32_t*)hs32)[idx] = f2tf32(hnew);
            if (s == SEQ - 1) hidden_f[(long)b2 * NHID + j0 + jj2] = hnew;
        }

        grid_barrier((unsigned)(s + 1));
    }
}

// ---------------- launch ----------------
extern "C" void kernel_launch(void* const* d_in, const int* in_sizes, int n_in,
                              void* d_out, int out_size)
{
    const int*   input  = (const int*)  d_in[0];
    const float* hidden = (const float*)d_in[1];
    const float* emb_W  = (const float*)d_in[2];
    const float* W_ih   = (const float*)d_in[3];
    const float* W_hh   = (const float*)d_in[4];
    const float* b_ih   = (const float*)d_in[5];
    const float* b_hh   = (const float*)d_in[6];
    const float* alpha  = (const float*)d_in[7];
    const float* dec_W  = (const float*)d_in[8];
    const float* dec_b  = (const float*)d_in[9];

    float* decoded  = (float*)d_out;                          // [S,B,NTOKEN]
    float* hidden_f = (float*)d_out + (long)MROWS * NTOKEN;   // [B,NHID]

    void *xin_p, *hs_p, *t32_p, *decw32_p, *wih32_p;
    cudaGetSymbolAddress(&xin_p,    g_xin);
    cudaGetSymbolAddress(&hs_p,     g_hs);
    cudaGetSymbolAddress(&t32_p,    g_t32buf);
    cudaGetSymbolAddress(&decw32_p, g_decW_t32);
    cudaGetSymbolAddress(&wih32_p,  g_wih_t32);
    float* xin     = (float*)xin_p;
    float* hs      = (float*)hs_p;
    float* t32     = (float*)t32_p;
    float* decw32  = (float*)decw32_p;
    float* wih32   = (float*)wih32_p;

    const int scan_smem = (8 * 1024 + 8 * 32 * 8) * (int)sizeof(float);
    cudaFuncSetAttribute(scan_kernel, cudaFuncAttributeMaxDynamicSharedMemorySize, scan_smem);
    cudaFuncSetAttribute(gemm_tf32_ldsm, cudaFuncAttributeMaxDynamicSharedMemorySize, DEC_SMEM);

    // 1) prep: dec_W/W_ih tf32 conversions + emb gather (tf32) + barrier reset
    prep_kernel<<<PREP_BLOCKS, 256>>>(dec_W, W_ih, emb_W, input);

    // 2) xin = emb @ W_ih^T + b_ih on tensor cores [4096 x 1024]
    gemm_tf32_ldsm<<<dim3(MROWS / DBM, NHID / DBN), 256, DEC_SMEM>>>(
        t32, wih32, b_ih, xin, MROWS, NHID, NINP);

    // 3) recurrence (fp32); emits tf32 hs into t32 and hidden_f directly
    scan_kernel<<<128, 256, scan_smem>>>(xin, hidden, W_hh, b_hh, alpha,
                                         hs, t32, hidden_f);

    // 4) decoder: decoded = hs @ dec_W^T + dec_b  [4096 x 32000]  (ncu target)
    gemm_tf32_ldsm<<<dim3(MROWS / DBM, NTOKEN / DBN), 256, DEC_SMEM>>>(
        t32, decw32, dec_b, decoded, MROWS, NTOKEN, NHID);
}

// round 8
// speedup vs baseline: 1.0575x; 1.0575x over previous
#include <cuda_runtime.h>
#include <cuda_bf16.h>
#include <math.h>
#include <stdint.h>

// Problem constants
#define SEQ    128
#define BATCH  32
#define NTOKEN 32000
#define NINP   1024
#define NHID   1024
#define MROWS  (SEQ * BATCH)          // 4096

// ---------------- scratch (no runtime allocation allowed) ----------------
__device__ float g_xin[MROWS * NHID];        // 16 MB
__device__ float g_hs [MROWS * NHID];        // 16 MB (fp32, scan-internal)
__device__ float g_t32buf[MROWS * NHID];     // 16 MB (tf32 bits: emb32 then hs32)
__device__ float g_decW_t32[NTOKEN * NHID];  // 131 MB (tf32 bits)
__device__ float g_wih_t32[NHID * NINP];     // 4 MB (tf32 bits)
__device__ unsigned g_arrive;
__device__ unsigned g_release;

// ---------------- helpers ----------------
__device__ __forceinline__ uint32_t smem_u32(const void* p) {
    return (uint32_t)__cvta_generic_to_shared(p);
}
__device__ __forceinline__ uint32_t f2tf32(float x) {
    uint32_t r;
    asm("cvt.rna.tf32.f32 %0, %1;" : "=r"(r) : "f"(x));
    return r;
}

#define LDSM_X4(r0, r1, r2, r3, addr) \
    asm volatile("ldmatrix.sync.aligned.m8n8.x4.shared.b16 {%0,%1,%2,%3}, [%4];" \
        : "=r"(r0), "=r"(r1), "=r"(r2), "=r"(r3) : "r"(addr))

// =============== prep: all conversions + gather + barrier reset =============
#define PREP_BLOCKS 2240

__global__ __launch_bounds__(256)
void prep_kernel(const float* __restrict__ dec_W,
                 const float* __restrict__ W_ih,
                 const float* __restrict__ emb_W,
                 const int*   __restrict__ input)
{
    const int bid = blockIdx.x;
    const int t   = threadIdx.x;
    if (bid == 0 && t == 0) { g_arrive = 0u; g_release = 0u; }

    if (bid < 2048) {
        const long n4 = (long)NTOKEN * NHID / 4;
        long i = (long)bid * 256 + t;
        const long stride = 2048L * 256;
        for (; i < n4; i += stride) {
            float4 v = ((const float4*)dec_W)[i];
            uint4 o = { f2tf32(v.x), f2tf32(v.y), f2tf32(v.z), f2tf32(v.w) };
            ((uint4*)g_decW_t32)[i] = o;
        }
    } else if (bid < 2112) {
        const long n4 = (long)NHID * NINP / 4;
        long i = (long)(bid - 2048) * 256 + t;
        const long stride = 64L * 256;
        for (; i < n4; i += stride) {
            float4 v = ((const float4*)W_ih)[i];
            uint4 o = { f2tf32(v.x), f2tf32(v.y), f2tf32(v.z), f2tf32(v.w) };
            ((uint4*)g_wih_t32)[i] = o;
        }
    } else {
        const long n4 = (long)MROWS * NINP / 4;
        long i = (long)(bid - 2112) * 256 + t;
        const long stride = 128L * 256;
        for (; i < n4; i += stride) {
            int row = (int)(i >> 8);          // NINP/4 = 256 float4 per row
            int c4  = (int)(i & 255);
            int tok = input[row];
            float4 v = *(const float4*)(emb_W + (long)tok * NINP + c4 * 4);
            uint4 o = { f2tf32(v.x), f2tf32(v.y), f2tf32(v.z), f2tf32(v.w) };
            *(uint4*)(g_t32buf + (long)row * NINP + c4 * 4) = o;
        }
    }
}

// ============ tf32 mma.sync GEMM with ldmatrix fragments ============
// C[M,N] = A[M,K]*B[N,K]^T + bias. CTA tile 128x128x32, 4 warps (64x64 each),
// 128 threads, 2 CTAs/SM (cross-CTA latency hiding at chunk boundaries).
// Smem: swizzled 128B rows, chunk' = kc ^ (row&7). 3 buffers, 2 groups in
// flight, ONE __syncthreads per chunk.
#define DBM 128
#define DBN 128
#define DBK 32
#define NSTG 3
#define NTHR 128
#define A_ST (DBM * DBK * 4)   // 16 KB
#define B_ST (DBN * DBK * 4)   // 16 KB
#define DEC_SMEM (NSTG * (A_ST + B_ST))   // 96 KB

__global__ __launch_bounds__(NTHR, 2)
void gemm_tf32_ldsm(const float* __restrict__ A,
                    const float* __restrict__ B,
                    const float* __restrict__ bias,
                    float*       __restrict__ C,
                    int M, int N, int K)
{
    extern __shared__ __align__(1024) char smem[];
    const uint32_t sA = smem_u32(smem);
    const uint32_t sB = sA + NSTG * A_ST;

    const int t    = threadIdx.x;
    const int warp = t >> 5;
    const int lane = t & 31;
    const int m0   = blockIdx.x * DBM;
    const int n0   = blockIdx.y * DBN;
    const int wm   = warp & 1;      // 2 m-subtiles of 64
    const int wn   = warp >> 1;     // 2 n-subtiles of 64
    const int g    = lane >> 2;
    const int tg   = lane & 3;

    // ldmatrix lane geometry
    const int mat = lane >> 3;      // 0..3
    const int sub = lane & 7;       // 0..7

    uint32_t aRowOff[4], aSw[4];
#pragma unroll
    for (int mi = 0; mi < 4; ++mi) {
        int r = wm * 64 + mi * 16 + (mat & 1) * 8 + sub;
        aRowOff[mi] = (uint32_t)(r * 128);
        aSw[mi]     = (uint32_t)(r & 7);
    }
    const uint32_t aMatK = (uint32_t)(mat >> 1);

    // B: 4 LDSM_X4, each covering two 8-row n-groups (2p, 2p+1), k split by mat>>1
    uint32_t bRowOff[4], bSw[4];
#pragma unroll
    for (int p = 0; p < 4; ++p) {
        int r = wn * 64 + (p * 2 + (mat >> 1)) * 8 + sub;
        bRowOff[p] = (uint32_t)(r * 128);
        bSw[p]     = (uint32_t)(r & 7);
    }
    const uint32_t bMatK = (uint32_t)(mat & 1);

    float acc[4][8][4];
#pragma unroll
    for (int mi = 0; mi < 4; ++mi)
#pragma unroll
        for (int ni = 0; ni < 8; ++ni)
#pragma unroll
            for (int r = 0; r < 4; ++r) acc[mi][ni][r] = 0.0f;

    auto load_chunk = [&](int c) {
        const int s  = c % NSTG;
        const int k0 = c * DBK;
        // A tile: 128 rows x 8 chunks = 1024 16B; 8 per thread
#pragma unroll
        for (int i = 0; i < 8; ++i) {
            int id  = t + i * NTHR;
            int row = id >> 3;
            int kc  = id & 7;
            uint32_t sw = (uint32_t)(row * 128 + ((kc ^ (row & 7)) << 4));
            uint32_t dst = sA + s * A_ST + sw;
            const float* ga = A + (long)(m0 + row) * K + k0 + kc * 4;
            asm volatile("cp.async.cg.shared.global [%0], [%1], 16;" :: "r"(dst), "l"(ga));
        }
        // B tile: 128 rows x 8 chunks = 1024 16B; 8 per thread
#pragma unroll
        for (int i = 0; i < 8; ++i) {
            int id  = t + i * NTHR;
            int row = id >> 3;
            int kc  = id & 7;
            uint32_t sw = (uint32_t)(row * 128 + ((kc ^ (row & 7)) << 4));
            uint32_t dst = sB + s * B_ST + sw;
            const float* gb = B + (long)(n0 + row) * K + k0 + kc * 4;
            asm volatile("cp.async.cg.shared.global [%0], [%1], 16;" :: "r"(dst), "l"(gb));
        }
        asm volatile("cp.async.commit_group;");
    };

    const int NCHUNK = K / DBK;   // 32
    load_chunk(0);
    load_chunk(1);

    for (int c = 0; c < NCHUNK; ++c) {
        const int buf = c % NSTG;
        asm volatile("cp.async.wait_group 1;");   // chunk c resident
        __syncthreads();                          // the ONLY sync per chunk

        // prefetch chunk c+2 into buf (c-1)%3 (finished by all warps)
        if (c + 2 < NCHUNK) {
            load_chunk(c + 2);
        } else {
            asm volatile("cp.async.commit_group;");   // uniform accounting
        }

        const uint32_t Ab = sA + buf * A_ST;
        const uint32_t Bb = sB + buf * B_ST;

#pragma unroll
        for (int kk = 0; kk < 4; ++kk) {
            uint32_t a[4][4];
            uint32_t b[8][2];
            const uint32_t cA = (uint32_t)(kk * 2) + aMatK;
            const uint32_t cB = (uint32_t)(kk * 2) + bMatK;
#pragma unroll
            for (int mi = 0; mi < 4; ++mi) {
                uint32_t addr = Ab + aRowOff[mi] + (((cA ^ aSw[mi])) << 4);
                LDSM_X4(a[mi][0], a[mi][1], a[mi][2], a[mi][3], addr);
            }
#pragma unroll
            for (int p = 0; p < 4; ++p) {
                uint32_t addr = Bb + bRowOff[p] + (((cB ^ bSw[p])) << 4);
                uint32_t r0, r1, r2, r3;
                LDSM_X4(r0, r1, r2, r3, addr);
                b[2 * p][0] = r0;     b[2 * p][1] = r1;
                b[2 * p + 1][0] = r2; b[2 * p + 1][1] = r3;
            }
#pragma unroll
            for (int mi = 0; mi < 4; ++mi)
#pragma unroll
                for (int ni = 0; ni < 8; ++ni) {
                    asm volatile(
                        "mma.sync.aligned.m16n8k8.row.col.f32.tf32.tf32.f32 "
                        "{%0,%1,%2,%3}, {%4,%5,%6,%7}, {%8,%9}, {%0,%1,%2,%3};\n"
                        : "+f"(acc[mi][ni][0]), "+f"(acc[mi][ni][1]),
                          "+f"(acc[mi][ni][2]), "+f"(acc[mi][ni][3])
                        : "r"(a[mi][0]), "r"(a[mi][1]), "r"(a[mi][2]), "r"(a[mi][3]),
                          "r"(b[ni][0]), "r"(b[ni][1]));
                }
        }
        // no trailing sync: next iteration's wait+sync provides the ordering
    }

    // ---- epilogue: add bias, store ----
#pragma unroll
    for (int mi = 0; mi < 4; ++mi) {
        int rbase = m0 + wm * 64 + mi * 16 + g;
#pragma unroll
        for (int ni = 0; ni < 8; ++ni) {
            int cc = n0 + wn * 64 + ni * 8 + 2 * tg;
            float b0 = bias[cc], b1 = bias[cc + 1];
            float2 v0 = make_float2(acc[mi][ni][0] + b0, acc[mi][ni][1] + b1);
            float2 v1 = make_float2(acc[mi][ni][2] + b0, acc[mi][ni][3] + b1);
            *(float2*)(C + (long)rbase * N + cc)       = v0;
            *(float2*)(C + (long)(rbase + 8) * N + cc) = v1;
        }
    }
}

// ---------------- persistent RNN scan ----------------
__device__ __forceinline__ void grid_barrier(unsigned gen) {
    __syncthreads();
    if (threadIdx.x == 0) {
        __threadfence();
        if (atomicAdd(&g_arrive, 1u) == gridDim.x - 1) {
            g_arrive = 0u;
            __threadfence();
            atomicExch(&g_release, gen);
        } else {
            while (*(volatile unsigned*)&g_release < gen) { }
        }
        __threadfence();
    }
    __syncthreads();
}

// Writes: hs (fp32), hs32 (tf32 bits), hidden_f at s == SEQ-1.
__global__ __launch_bounds__(256)
void scan_kernel(const float* __restrict__ xin,
                 const float* __restrict__ h0,
                 const float* __restrict__ W_hh,
                 const float* __restrict__ b_hh,
                 const float* __restrict__ alpha,
                 float*       __restrict__ hs,
                 float*       __restrict__ hs32,
                 float*       __restrict__ hidden_f)
{
    extern __shared__ float sm[];
    float* Wsh = sm;                  // 8 * 1024
    float* red = sm + 8 * 1024;       // 8 * 32 * 8

    const int t  = threadIdx.x;
    const int jb = blockIdx.x;
    const int j0 = jb * 8;

    {
        const float4* src = (const float4*)(W_hh + (long)j0 * NHID);
        float4* dst = (float4*)Wsh;
        for (int i = t; i < 8 * NHID / 4; i += 256) dst[i] = src[i];
    }
    __syncthreads();

    const int kg = t >> 5;
    const int b  = t & 31;
    const int b2  = t >> 3;
    const int jj2 = t & 7;
    const float bh = b_hh[j0 + jj2];

    for (int s = 0; s < SEQ; ++s) {
        const float* hprev = (s == 0) ? h0 : (hs + (long)(s - 1) * BATCH * NHID);

        float acc[8];
#pragma unroll
        for (int jj = 0; jj < 8; ++jj) acc[jj] = 0.0f;

        const float* hrow  = hprev + (long)b * NHID + kg * 128;
        const float* wbase = &Wsh[kg * 128];
#pragma unroll 8
        for (int k = 0; k < 128; k += 4) {
            float4 hv = *(const float4*)&hrow[k];
#pragma unroll
            for (int jj = 0; jj < 8; ++jj) {
                float4 wv = *(const float4*)&wbase[jj * NHID + k];
                acc[jj] += hv.x * wv.x + hv.y * wv.y + hv.z * wv.z + hv.w * wv.w;
            }
        }

#pragma unroll
        for (int jj = 0; jj < 8; ++jj) red[(kg * 32 + b) * 8 + jj] = acc[jj];
        __syncthreads();

        {
            float sum = 0.0f;
#pragma unroll
            for (int kk = 0; kk < 8; ++kk) sum += red[(kk * 32 + b2) * 8 + jj2];
            long idx = (long)(s * BATCH + b2) * NHID + j0 + jj2;
            float val = xin[idx] + sum + bh;
            float hnew = alpha[s] * tanhf(val);
            hs[idx] = hnew;
            ((uint32_t*)hs32)[idx] = f2tf32(hnew);
            if (s == SEQ - 1) hidden_f[(long)b2 * NHID + j0 + jj2] = hnew;
        }

        grid_barrier((unsigned)(s + 1));
    }
}

// ---------------- launch ----------------
extern "C" void kernel_launch(void* const* d_in, const int* in_sizes, int n_in,
                              void* d_out, int out_size)
{
    const int*   input  = (const int*)  d_in[0];
    const float* hidden = (const float*)d_in[1];
    const float* emb_W  = (const float*)d_in[2];
    const float* W_ih   = (const float*)d_in[3];
    const float* W_hh   = (const float*)d_in[4];
    const float* b_ih   = (const float*)d_in[5];
    const float* b_hh   = (const float*)d_in[6];
    const float* alpha  = (const float*)d_in[7];
    const float* dec_W  = (const float*)d_in[8];
    const float* dec_b  = (const float*)d_in[9];

    float* decoded  = (float*)d_out;                          // [S,B,NTOKEN]
    float* hidden_f = (float*)d_out + (long)MROWS * NTOKEN;   // [B,NHID]

    void *xin_p, *hs_p, *t32_p, *decw32_p, *wih32_p;
    cudaGetSymbolAddress(&xin_p,    g_xin);
    cudaGetSymbolAddress(&hs_p,     g_hs);
    cudaGetSymbolAddress(&t32_p,    g_t32buf);
    cudaGetSymbolAddress(&decw32_p, g_decW_t32);
    cudaGetSymbolAddress(&wih32_p,  g_wih_t32);
    float* xin     = (float*)xin_p;
    float* hs      = (float*)hs_p;
    float* t32     = (float*)t32_p;
    float* decw32  = (float*)decw32_p;
    float* wih32   = (float*)wih32_p;

    const int scan_smem = (8 * 1024 + 8 * 32 * 8) * (int)sizeof(float);
    cudaFuncSetAttribute(scan_kernel, cudaFuncAttributeMaxDynamicSharedMemorySize, scan_smem);
    cudaFuncSetAttribute(gemm_tf32_ldsm, cudaFuncAttributeMaxDynamicSharedMemorySize, DEC_SMEM);

    // 1) prep: dec_W/W_ih tf32 conversions + emb gather (tf32) + barrier reset
    prep_kernel<<<PREP_BLOCKS, 256>>>(dec_W, W_ih, emb_W, input);

    // 2) xin = emb @ W_ih^T + b_ih on tensor cores [4096 x 1024]
    gemm_tf32_ldsm<<<dim3(MROWS / DBM, NHID / DBN), NTHR, DEC_SMEM>>>(
        t32, wih32, b_ih, xin, MROWS, NHID, NINP);

    // 3) recurrence (fp32); emits tf32 hs into t32 and hidden_f directly
    scan_kernel<<<128, 256, scan_smem>>>(xin, hidden, W_hh, b_hh, alpha,
                                         hs, t32, hidden_f);

    // 4) decoder: decoded = hs @ dec_W^T + dec_b  [4096 x 32000]  (ncu target)
    gemm_tf32_ldsm<<<dim3(MROWS / DBM, NTOKEN / DBN), NTHR, DEC_SMEM>>>(
        t32, decw32, dec_b, decoded, MROWS, NTOKEN, NHID);
}

// round 9
// speedup vs baseline: 1.0647x; 1.0068x over previous
#include <cuda_runtime.h>
#include <cuda_bf16.h>
#include <math.h>
#include <stdint.h>
#include <string.h>

// Problem constants
#define SEQ    128
#define BATCH  32
#define NTOKEN 32000
#define NINP   1024
#define NHID   1024
#define MROWS  (SEQ * BATCH)          // 4096

// ---------------- scratch (no runtime allocation allowed) ----------------
__device__ float g_xin[MROWS * NHID];        // 16 MB
__device__ float g_hs [MROWS * NHID];        // 16 MB (fp32, scan-internal)
__device__ float g_t32buf[MROWS * NHID];     // 16 MB (tf32 bits: emb32 then hs32)
__device__ float g_decW_t32[NTOKEN * NHID];  // 131 MB (tf32 bits)
__device__ float g_wih_t32[NHID * NINP];     // 4 MB (tf32 bits)
__device__ unsigned g_arrive;
__device__ unsigned g_release;

// ---------------- helpers ----------------
__device__ __forceinline__ uint32_t smem_u32(const void* p) {
    return (uint32_t)__cvta_generic_to_shared(p);
}
__device__ __forceinline__ uint32_t f2tf32(float x) {
    uint32_t r;
    asm("cvt.rna.tf32.f32 %0, %1;" : "=r"(r) : "f"(x));
    return r;
}

#define LDSM_X4(r0, r1, r2, r3, addr) \
    asm volatile("ldmatrix.sync.aligned.m8n8.x4.shared.b16 {%0,%1,%2,%3}, [%4];" \
        : "=r"(r0), "=r"(r1), "=r"(r2), "=r"(r3) : "r"(addr))

#define FMA_X2(acc, a, b) \
    asm volatile("fma.rn.f32x2 %0, %1, %2, %0;" : "+l"(acc) : "l"(a), "l"(b))

// =============== prep_a: dec_W -> tf32 (the big conversion) =============
__global__ __launch_bounds__(256)
void prep_a_kernel(const float* __restrict__ dec_W)
{
    const long n4 = (long)NTOKEN * NHID / 4;
    long i = (long)blockIdx.x * 256 + threadIdx.x;
    const long stride = (long)gridDim.x * 256;
    for (; i < n4; i += stride) {
        float4 v = ((const float4*)dec_W)[i];
        uint4 o = { f2tf32(v.x), f2tf32(v.y), f2tf32(v.z), f2tf32(v.w) };
        ((uint4*)g_decW_t32)[i] = o;
    }
}

// =============== prep_b: W_ih cvt + emb gather + barrier reset =============
// blocks [0, 64)   : cvt W_ih  -> g_wih_t32
// blocks [64, 192) : gather emb_W[input] -> g_t32buf (tf32)
#define PREP_B_BLOCKS 192

__global__ __launch_bounds__(256)
void prep_b_kernel(const float* __restrict__ W_ih,
                   const float* __restrict__ emb_W,
                   const int*   __restrict__ input)
{
    const int bid = blockIdx.x;
    const int t   = threadIdx.x;
    if (bid == 0 && t == 0) { g_arrive = 0u; g_release = 0u; }

    if (bid < 64) {
        const long n4 = (long)NHID * NINP / 4;
        long i = (long)bid * 256 + t;
        const long stride = 64L * 256;
        for (; i < n4; i += stride) {
            float4 v = ((const float4*)W_ih)[i];
            uint4 o = { f2tf32(v.x), f2tf32(v.y), f2tf32(v.z), f2tf32(v.w) };
            ((uint4*)g_wih_t32)[i] = o;
        }
    } else {
        const long n4 = (long)MROWS * NINP / 4;
        long i = (long)(bid - 64) * 256 + t;
        const long stride = 128L * 256;
        for (; i < n4; i += stride) {
            int row = (int)(i >> 8);          // NINP/4 = 256 float4 per row
            int c4  = (int)(i & 255);
            int tok = input[row];
            float4 v = *(const float4*)(emb_W + (long)tok * NINP + c4 * 4);
            uint4 o = { f2tf32(v.x), f2tf32(v.y), f2tf32(v.z), f2tf32(v.w) };
            *(uint4*)(g_t32buf + (long)row * NINP + c4 * 4) = o;
        }
    }
}

// ============ tf32 mma.sync GEMM with ldmatrix fragments ============
// C[M,N] = A[M,K]*B[N,K]^T + bias. CTA tile 128x128x32, 4 warps (64x64 each),
// 128 threads, 2 CTAs/SM. Swizzled 128B smem rows, 3 buffers, 2 groups in
// flight, ONE __syncthreads per chunk.
#define DBM 128
#define DBN 128
#define DBK 32
#define NSTG 3
#define NTHR 128
#define A_ST (DBM * DBK * 4)   // 16 KB
#define B_ST (DBN * DBK * 4)   // 16 KB
#define DEC_SMEM (NSTG * (A_ST + B_ST))   // 96 KB

__global__ __launch_bounds__(NTHR, 2)
void gemm_tf32_ldsm(const float* __restrict__ A,
                    const float* __restrict__ B,
                    const float* __restrict__ bias,
                    float*       __restrict__ C,
                    int M, int N, int K)
{
    extern __shared__ __align__(1024) char smem[];
    const uint32_t sA = smem_u32(smem);
    const uint32_t sB = sA + NSTG * A_ST;

    const int t    = threadIdx.x;
    const int warp = t >> 5;
    const int lane = t & 31;
    const int m0   = blockIdx.x * DBM;
    const int n0   = blockIdx.y * DBN;
    const int wm   = warp & 1;      // 2 m-subtiles of 64
    const int wn   = warp >> 1;     // 2 n-subtiles of 64
    const int g    = lane >> 2;
    const int tg   = lane & 3;

    const int mat = lane >> 3;      // 0..3
    const int sub = lane & 7;       // 0..7

    uint32_t aRowOff[4], aSw[4];
#pragma unroll
    for (int mi = 0; mi < 4; ++mi) {
        int r = wm * 64 + mi * 16 + (mat & 1) * 8 + sub;
        aRowOff[mi] = (uint32_t)(r * 128);
        aSw[mi]     = (uint32_t)(r & 7);
    }
    const uint32_t aMatK = (uint32_t)(mat >> 1);

    uint32_t bRowOff[4], bSw[4];
#pragma unroll
    for (int p = 0; p < 4; ++p) {
        int r = wn * 64 + (p * 2 + (mat >> 1)) * 8 + sub;
        bRowOff[p] = (uint32_t)(r * 128);
        bSw[p]     = (uint32_t)(r & 7);
    }
    const uint32_t bMatK = (uint32_t)(mat & 1);

    float acc[4][8][4];
#pragma unroll
    for (int mi = 0; mi < 4; ++mi)
#pragma unroll
        for (int ni = 0; ni < 8; ++ni)
#pragma unroll
            for (int r = 0; r < 4; ++r) acc[mi][ni][r] = 0.0f;

    auto load_chunk = [&](int c) {
        const int s  = c % NSTG;
        const int k0 = c * DBK;
#pragma unroll
        for (int i = 0; i < 8; ++i) {
            int id  = t + i * NTHR;
            int row = id >> 3;
            int kc  = id & 7;
            uint32_t sw = (uint32_t)(row * 128 + ((kc ^ (row & 7)) << 4));
            uint32_t dst = sA + s * A_ST + sw;
            const float* ga = A + (long)(m0 + row) * K + k0 + kc * 4;
            asm volatile("cp.async.cg.shared.global [%0], [%1], 16;" :: "r"(dst), "l"(ga));
        }
#pragma unroll
        for (int i = 0; i < 8; ++i) {
            int id  = t + i * NTHR;
            int row = id >> 3;
            int kc  = id & 7;
            uint32_t sw = (uint32_t)(row * 128 + ((kc ^ (row & 7)) << 4));
            uint32_t dst = sB + s * B_ST + sw;
            const float* gb = B + (long)(n0 + row) * K + k0 + kc * 4;
            asm volatile("cp.async.cg.shared.global [%0], [%1], 16;" :: "r"(dst), "l"(gb));
        }
        asm volatile("cp.async.commit_group;");
    };

    const int NCHUNK = K / DBK;   // 32
    load_chunk(0);
    load_chunk(1);

    for (int c = 0; c < NCHUNK; ++c) {
        const int buf = c % NSTG;
        asm volatile("cp.async.wait_group 1;");
        __syncthreads();

        if (c + 2 < NCHUNK) {
            load_chunk(c + 2);
        } else {
            asm volatile("cp.async.commit_group;");
        }

        const uint32_t Ab = sA + buf * A_ST;
        const uint32_t Bb = sB + buf * B_ST;

#pragma unroll
        for (int kk = 0; kk < 4; ++kk) {
            uint32_t a[4][4];
            uint32_t b[8][2];
            const uint32_t cA = (uint32_t)(kk * 2) + aMatK;
            const uint32_t cB = (uint32_t)(kk * 2) + bMatK;
#pragma unroll
            for (int mi = 0; mi < 4; ++mi) {
                uint32_t addr = Ab + aRowOff[mi] + (((cA ^ aSw[mi])) << 4);
                LDSM_X4(a[mi][0], a[mi][1], a[mi][2], a[mi][3], addr);
            }
#pragma unroll
            for (int p = 0; p < 4; ++p) {
                uint32_t addr = Bb + bRowOff[p] + (((cB ^ bSw[p])) << 4);
                uint32_t r0, r1, r2, r3;
                LDSM_X4(r0, r1, r2, r3, addr);
                b[2 * p][0] = r0;     b[2 * p][1] = r1;
                b[2 * p + 1][0] = r2; b[2 * p + 1][1] = r3;
            }
#pragma unroll
            for (int mi = 0; mi < 4; ++mi)
#pragma unroll
                for (int ni = 0; ni < 8; ++ni) {
                    asm volatile(
                        "mma.sync.aligned.m16n8k8.row.col.f32.tf32.tf32.f32 "
                        "{%0,%1,%2,%3}, {%4,%5,%6,%7}, {%8,%9}, {%0,%1,%2,%3};\n"
                        : "+f"(acc[mi][ni][0]), "+f"(acc[mi][ni][1]),
                          "+f"(acc[mi][ni][2]), "+f"(acc[mi][ni][3])
                        : "r"(a[mi][0]), "r"(a[mi][1]), "r"(a[mi][2]), "r"(a[mi][3]),
                          "r"(b[ni][0]), "r"(b[ni][1]));
                }
        }
    }

    // ---- epilogue: add bias, store ----
#pragma unroll
    for (int mi = 0; mi < 4; ++mi) {
        int rbase = m0 + wm * 64 + mi * 16 + g;
#pragma unroll
        for (int ni = 0; ni < 8; ++ni) {
            int cc = n0 + wn * 64 + ni * 8 + 2 * tg;
            float b0 = bias[cc], b1 = bias[cc + 1];
            float2 v0 = make_float2(acc[mi][ni][0] + b0, acc[mi][ni][1] + b1);
            float2 v1 = make_float2(acc[mi][ni][2] + b0, acc[mi][ni][3] + b1);
            *(float2*)(C + (long)rbase * N + cc)       = v0;
            *(float2*)(C + (long)(rbase + 8) * N + cc) = v1;
        }
    }
}

// ---------------- persistent RNN scan ----------------
// Scoped-atomics grid barrier: monotonic arrive counter (release), leader
// publishes generation (release), pollers spin on acquire load. No resets
// between generations (prep_b zeroes the counters each launch/replay).
#define SCAN_NB 128u

__device__ __forceinline__ void grid_barrier(unsigned gen) {
    __syncthreads();
    if (threadIdx.x == 0) {
        unsigned old;
        asm volatile("atom.add.release.gpu.global.u32 %0, [%1], %2;"
                     : "=r"(old) : "l"(&g_arrive), "r"(1u) : "memory");
        if (old == gen * SCAN_NB - 1u) {
            asm volatile("st.release.gpu.global.u32 [%0], %1;"
                         :: "l"(&g_release), "r"(gen) : "memory");
        } else {
            unsigned r;
            do {
                asm volatile("ld.acquire.gpu.global.u32 %0, [%1];"
                             : "=r"(r) : "l"(&g_release) : "memory");
            } while (r < gen);
        }
    }
    __syncthreads();
}

// Writes: hs (fp32), hs32 (tf32 bits), hidden_f at s == SEQ-1.
__global__ __launch_bounds__(256)
void scan_kernel(const float* __restrict__ xin,
                 const float* __restrict__ h0,
                 const float* __restrict__ W_hh,
                 const float* __restrict__ b_hh,
                 const float* __restrict__ alpha,
                 float*       __restrict__ hs,
                 float*       __restrict__ hs32,
                 float*       __restrict__ hidden_f)
{
    extern __shared__ float sm[];
    float* Wsh = sm;                  // 8 * 1024
    float* red = sm + 8 * 1024;       // 8 * 32 * 8

    const int t  = threadIdx.x;
    const int jb = blockIdx.x;
    const int j0 = jb * 8;

    {
        const float4* src = (const float4*)(W_hh + (long)j0 * NHID);
        float4* dst = (float4*)Wsh;
        for (int i = t; i < 8 * NHID / 4; i += 256) dst[i] = src[i];
    }
    __syncthreads();

    const int kg = t >> 5;
    const int b  = t & 31;
    const int b2  = t >> 3;
    const int jj2 = t & 7;
    const float bh = b_hh[j0 + jj2];

    for (int s = 0; s < SEQ; ++s) {
        const float* hprev = (s == 0) ? h0 : (hs + (long)(s - 1) * BATCH * NHID);

        // packed f32x2 partial sums: (even-k, odd-k)
        unsigned long long accP[8];
#pragma unroll
        for (int jj = 0; jj < 8; ++jj) accP[jj] = 0ull;

        const float* hrow  = hprev + (long)b * NHID + kg * 128;
        const float* wbase = &Wsh[kg * 128];
#pragma unroll 4
        for (int k = 0; k < 128; k += 4) {
            ulonglong2 hq = *(const ulonglong2*)&hrow[k];
#pragma unroll
            for (int jj = 0; jj < 8; ++jj) {
                ulonglong2 wq = *(const ulonglong2*)&wbase[jj * NHID + k];
                FMA_X2(accP[jj], hq.x, wq.x);
                FMA_X2(accP[jj], hq.y, wq.y);
            }
        }

#pragma unroll
        for (int jj = 0; jj < 8; ++jj) {
            float2 f;
            memcpy(&f, &accP[jj], 8);
            red[(kg * 32 + b) * 8 + jj] = f.x + f.y;
        }
        __syncthreads();

        {
            float sum = 0.0f;
#pragma unroll
            for (int kk = 0; kk < 8; ++kk) sum += red[(kk * 32 + b2) * 8 + jj2];
            long idx = (long)(s * BATCH + b2) * NHID + j0 + jj2;
            float val = xin[idx] + sum + bh;
            float hnew = alpha[s] * tanhf(val);
            hs[idx] = hnew;
            ((uint32_t*)hs32)[idx] = f2tf32(hnew);
            if (s == SEQ - 1) hidden_f[(long)b2 * NHID + j0 + jj2] = hnew;
        }

        grid_barrier((unsigned)(s + 1));
    }
}

// ---------------- launch ----------------
extern "C" void kernel_launch(void* const* d_in, const int* in_sizes, int n_in,
                              void* d_out, int out_size)
{
    const int*   input  = (const int*)  d_in[0];
    const float* hidden = (const float*)d_in[1];
    const float* emb_W  = (const float*)d_in[2];
    const float* W_ih   = (const float*)d_in[3];
    const float* W_hh   = (const float*)d_in[4];
    const float* b_ih   = (const float*)d_in[5];
    const float* b_hh   = (const float*)d_in[6];
    const float* alpha  = (const float*)d_in[7];
    const float* dec_W  = (const float*)d_in[8];
    const float* dec_b  = (const float*)d_in[9];

    float* decoded  = (float*)d_out;                          // [S,B,NTOKEN]
    float* hidden_f = (float*)d_out + (long)MROWS * NTOKEN;   // [B,NHID]

    void *xin_p, *hs_p, *t32_p, *decw32_p, *wih32_p;
    cudaGetSymbolAddress(&xin_p,    g_xin);
    cudaGetSymbolAddress(&hs_p,     g_hs);
    cudaGetSymbolAddress(&t32_p,    g_t32buf);
    cudaGetSymbolAddress(&decw32_p, g_decW_t32);
    cudaGetSymbolAddress(&wih32_p,  g_wih_t32);
    float* xin     = (float*)xin_p;
    float* hs      = (float*)hs_p;
    float* t32     = (float*)t32_p;
    float* decw32  = (float*)decw32_p;
    float* wih32   = (float*)wih32_p;

    const int scan_smem = (8 * 1024 + 8 * 32 * 8) * (int)sizeof(float);
    cudaFuncSetAttribute(scan_kernel, cudaFuncAttributeMaxDynamicSharedMemorySize, scan_smem);
    cudaFuncSetAttribute(gemm_tf32_ldsm, cudaFuncAttributeMaxDynamicSharedMemorySize, DEC_SMEM);

    // 1) prep_a: dec_W -> tf32
    prep_a_kernel<<<2048, 256>>>(dec_W);

    // 2) prep_b: W_ih cvt + emb gather + barrier counter reset
    prep_b_kernel<<<PREP_B_BLOCKS, 256>>>(W_ih, emb_W, input);

    // 3) xin = emb @ W_ih^T + b_ih on tensor cores [4096 x 1024]
    gemm_tf32_ldsm<<<dim3(MROWS / DBM, NHID / DBN), NTHR, DEC_SMEM>>>(
        t32, wih32, b_ih, xin, MROWS, NHID, NINP);

    // 4) recurrence (fp32 + f32x2) — 4th launch: ncu target this round
    scan_kernel<<<SCAN_NB, 256, scan_smem>>>(xin, hidden, W_hh, b_hh, alpha,
                                             hs, t32, hidden_f);

    // 5) decoder: decoded = hs @ dec_W^T + dec_b  [4096 x 32000]
    gemm_tf32_ldsm<<<dim3(MROWS / DBM, NTOKEN / DBN), NTHR, DEC_SMEM>>>(
        t32, decw32, dec_b, decoded, MROWS, NTOKEN, NHID);
}